// round 15
// baseline (speedup 1.0000x reference)
#include <cuda_runtime.h>
#include <cuda_bf16.h>
#include <math.h>
#include <stdint.h>

// SequenceAttLayer: B=4096, T=200, H=64; MLP 256->80->40->1, masked softmax, att@keys.
// Algebra: x=[q,k,q-k,q*k];  x.W1 = k.(W1b-W1c + diag(q).W1d) + [q.(W1a+W1c)+b1]
// Round 15: sigmoid -> tanh.approx with affine parts folded into weights:
//   sig(z) = 1/2 + 1/2 tanh(z/2);  layer2 uses A=tau, B=W2/2, bias r=(b2+SumW2/2)/2;
//   head: Wd*sig = q*(1+tanh(fma(.5,acc,r))), q=Wd/2. Scalar epilogue slots -38%.
// Structure otherwise = round 14 (fused layers, 128-row chunks, 4 CTAs/SM).

#define T_DIM 200
#define H_DIM 64
#define D1 80
#define D2 40

#define K_STR   72
#define WT_STR  72
#define W2T_STR 88

// shared layout (float offsets; bf16 regions are 2x elements)
#define OFF_KS    0        // 128*72 bf16 = 4608 f
#define OFF_WT    4608     // 80*72 bf16 = 2880 f
#define OFF_W2T   7488     // 40*88 bf16 = 1760 f
#define OFF_C     9248     // 160 (two halves, pre-scaled by 1/2)
#define OFF_B2    9408     // 40 (r_n)
#define OFF_WD    9448     // 40 (q_n)
#define OFF_Q     9488     // 64
#define OFF_SC    9552     // 256
#define OFF_RED   9808     // 8
#define OFF_RED2  9816     // 8
#define OFF_OBUF  9824     // 16*64 = 1024
#define SMEM_FLOATS 10848  // 43392 B -> 4 CTAs/SM

typedef __nv_bfloat16 bf16;

__device__ __forceinline__ uint32_t cvsm(const void* p) {
    return (uint32_t)__cvta_generic_to_shared(p);
}
__device__ __forceinline__ void ldm_x4(uint32_t& r0, uint32_t& r1,
                                       uint32_t& r2, uint32_t& r3, uint32_t a) {
    asm volatile("ldmatrix.sync.aligned.m8n8.x4.shared.b16 {%0,%1,%2,%3}, [%4];"
                 : "=r"(r0), "=r"(r1), "=r"(r2), "=r"(r3) : "r"(a));
}
__device__ __forceinline__ void ldm_x2(uint32_t& r0, uint32_t& r1, uint32_t a) {
    asm volatile("ldmatrix.sync.aligned.m8n8.x2.shared.b16 {%0,%1}, [%2];"
                 : "=r"(r0), "=r"(r1) : "r"(a));
}
__device__ __forceinline__ void mma16(float& d0, float& d1, float& d2, float& d3,
                                      uint32_t a0, uint32_t a1, uint32_t a2, uint32_t a3,
                                      uint32_t b0, uint32_t b1) {
    asm("mma.sync.aligned.m16n8k16.row.col.f32.bf16.bf16.f32 "
        "{%0,%1,%2,%3}, {%4,%5,%6,%7}, {%8,%9}, {%0,%1,%2,%3};"
        : "+f"(d0), "+f"(d1), "+f"(d2), "+f"(d3)
        : "r"(a0), "r"(a1), "r"(a2), "r"(a3), "r"(b0), "r"(b1));
}
__device__ __forceinline__ uint32_t pack_bf16(float lo, float hi) {
    uint32_t r;
    asm("cvt.rn.bf16x2.f32 %0, %1, %2;" : "=r"(r) : "f"(hi), "f"(lo));
    return r;
}
__device__ __forceinline__ float ex2f(float x) {
    float r;
    asm("ex2.approx.f32 %0, %1;" : "=f"(r) : "f"(x));
    return r;
}
__device__ __forceinline__ float tanhap(float x) {
    float r;
    asm("tanh.approx.f32 %0, %1;" : "=f"(r) : "f"(x));
    return r;
}

__global__ __launch_bounds__(256, 4)
void seqatt_kernel(const float* __restrict__ queries,
                   const float* __restrict__ keys,
                   const int* __restrict__ keys_length,
                   const float* __restrict__ W1,
                   const float* __restrict__ b1,
                   const float* __restrict__ W2,
                   const float* __restrict__ b2,
                   const float* __restrict__ Wd,
                   float* __restrict__ out)
{
    extern __shared__ float sm[];
    bf16* K_s   = reinterpret_cast<bf16*>(sm + OFF_KS);
    bf16* W_t   = reinterpret_cast<bf16*>(sm + OFF_WT);
    bf16* W2_t  = reinterpret_cast<bf16*>(sm + OFF_W2T);
    float* c_s  = sm + OFF_C;
    float* b2_s = sm + OFF_B2;
    float* Wd_s = sm + OFF_WD;
    float* q_s  = sm + OFF_Q;
    float* sc   = sm + OFF_SC;
    float* red  = sm + OFF_RED;
    float* red2 = sm + OFF_RED2;
    float* obuf = sm + OFF_OBUF;

    const int b   = blockIdx.x;
    const int tid = threadIdx.x;
    // keys_length is int32 on device (JAX x64-disabled downcasts int64->int32).
    int len = keys_length[b];
    len = len < 1 ? 1 : (len > T_DIM ? T_DIM : len);

    // ---- phase 0 ----
    if (tid < H_DIM) q_s[tid] = queries[b * H_DIM + tid];
    if (tid < D2) {
        // r_n = (b2 + kappa)/2, kappa = (1/2) Sum_j W2[j][n];  q_n = Wd/2
        float kap = 0.f;
        #pragma unroll 8
        for (int j = 0; j < D1; j++) kap += W2[j * D2 + tid];
        b2_s[tid] = 0.5f * (b2[tid] + 0.5f * kap);
        Wd_s[tid] = 0.5f * Wd[tid];
    }
    for (int i = tid; i < D1 * (D2 / 2); i += 256) {     // W2_t[n][j] = W2[j][n]/2
        int j = i / (D2 / 2), n2 = i - j * (D2 / 2);
        float2 v = *reinterpret_cast<const float2*>(W2 + j * D2 + 2 * n2);
        W2_t[(2 * n2)     * W2T_STR + j] = __float2bfloat16(0.5f * v.x);
        W2_t[(2 * n2 + 1) * W2T_STR + j] = __float2bfloat16(0.5f * v.y);
    }
    __syncthreads();

    for (int i = tid; i < H_DIM * (D1 / 2); i += 256) {  // W_t[j][h]
        int h = i / (D1 / 2), j2 = i - h * (D1 / 2);
        float2 wb = *reinterpret_cast<const float2*>(W1 + (64  + h) * D1 + 2 * j2);
        float2 wc = *reinterpret_cast<const float2*>(W1 + (128 + h) * D1 + 2 * j2);
        float2 wd = *reinterpret_cast<const float2*>(W1 + (192 + h) * D1 + 2 * j2);
        float qh = q_s[h];
        W_t[(2 * j2)     * WT_STR + h] = __float2bfloat16(wb.x - wc.x + qh * wd.x);
        W_t[(2 * j2 + 1) * WT_STR + h] = __float2bfloat16(wb.y - wc.y + qh * wd.y);
    }
    if (tid < 160) {   // c halves, pre-scaled by 1/2; summed in the layer-1 epilogue
        int seg = (tid >= 80) ? 1 : 0;
        int j = tid - 80 * seg;
        float acc = seg ? 0.f : b1[j];
        const float* p1 = W1 + (32 * seg) * D1 + j;
        const float* p2 = W1 + (128 + 32 * seg) * D1 + j;
        const float* qq = q_s + 32 * seg;
        #pragma unroll 8
        for (int h = 0; h < 32; h++)
            acc += qq[h] * (p1[h * D1] + p2[h * D1]);
        c_s[seg * 80 + j] = 0.5f * acc;
    }

    const int w    = tid >> 5;        // warp owns rows 16w..16w+15 of the chunk
    const int lane = tid & 31;
    const int gid  = lane >> 2;
    const int tig  = lane & 3;

    const int r8  = lane & 7;
    const int mi  = lane >> 3;
    const int mi2 = mi & 1;

    const uint32_t aA = cvsm(K_s) + 2 * ((16 * w + r8 + ((mi & 1) << 3)) * K_STR + ((mi >> 1) << 3));
    const uint32_t aB01 = cvsm(W_t) + 2 * ((8 * (mi >> 1) + r8) * WT_STR + ((mi & 1) << 3));
    const uint32_t aB23 = aB01 + 2 * (16 * WT_STR);
    const uint32_t aB4  = cvsm(W_t) + 2 * ((8 * 4 + r8) * WT_STR + (mi2 << 3));
    const uint32_t NBH  = 2 * (40 * WT_STR);   // bytes per n-half (5 tiles)
    const uint32_t aC01 = cvsm(W2_t) + 2 * ((8 * (mi >> 1) + r8) * W2T_STR + ((mi & 1) << 3));
    const uint32_t aC23 = aC01 + 2 * (16 * W2T_STR);
    const uint32_t aC4  = cvsm(W2_t) + 2 * ((8 * 4 + r8) * W2T_STR + (mi2 << 3));

    const float* Kbase = keys + (size_t)b * T_DIM * H_DIM;
    const int nchunk = (len + 127) >> 7;    // 1 or 2

    const int srow = tid >> 4;
    const int scol = (tid & 15) << 2;
    bf16* sdst0 = K_s + srow * K_STR + scol;

    // ---- prologue: stage chunk 0 (rows 0..127, in-bounds) ----
    {
        const float* g0 = Kbase + srow * H_DIM + scol;
        #pragma unroll
        for (int it = 0; it < 8; it++) {
            float4 f = *reinterpret_cast<const float4*>(g0 + it * (16 * H_DIM));
            uint2 u;
            u.x = pack_bf16(f.x, f.y);
            u.y = pack_bf16(f.z, f.w);
            *reinterpret_cast<uint2*>(sdst0 + it * (16 * K_STR)) = u;
        }
    }

    for (int ch = 0; ch < nchunk; ch++) {
        const int t0 = ch << 7;
        const bool active = (16 * w) < (len - t0);   // warp-uniform tail skip

        __syncthreads();   // A: K_s ready (at ch0 also fences phase-0 W_t/c)

        if (active) {
            // ---- layer 1: two n-half passes; tau packed into layer-2 A-frags ----
            uint32_t pk_lo[10], pk_hi[10];
            #pragma unroll
            for (int nh = 0; nh < 2; nh++) {
                float acc1[5][4];
                #pragma unroll
                for (int nt = 0; nt < 5; nt++)
                    #pragma unroll
                    for (int i = 0; i < 4; i++) acc1[nt][i] = 0.f;

                const uint32_t bb0 = aB01 + nh * NBH;
                const uint32_t bb2 = aB23 + nh * NBH;
                const uint32_t bb4 = aB4  + nh * NBH;
                #pragma unroll
                for (int ks = 0; ks < 4; ks++) {
                    const uint32_t off = 32 * ks;
                    uint32_t a0, a1, a2, a3;
                    ldm_x4(a0, a1, a2, a3, aA + off);
                    uint32_t b0, b1r, b2r, b3;
                    ldm_x4(b0, b1r, b2r, b3, bb0 + off);
                    mma16(acc1[0][0], acc1[0][1], acc1[0][2], acc1[0][3], a0, a1, a2, a3, b0, b1r);
                    mma16(acc1[1][0], acc1[1][1], acc1[1][2], acc1[1][3], a0, a1, a2, a3, b2r, b3);
                    ldm_x4(b0, b1r, b2r, b3, bb2 + off);
                    mma16(acc1[2][0], acc1[2][1], acc1[2][2], acc1[2][3], a0, a1, a2, a3, b0, b1r);
                    mma16(acc1[3][0], acc1[3][1], acc1[3][2], acc1[3][3], a0, a1, a2, a3, b2r, b3);
                    ldm_x2(b0, b1r, bb4 + off);
                    mma16(acc1[4][0], acc1[4][1], acc1[4][2], acc1[4][3], a0, a1, a2, a3, b0, b1r);
                }
                #pragma unroll
                for (int nt = 0; nt < 5; nt++) {
                    const int gn = 5 * nh + nt;
                    const int n0 = 8 * gn + 2 * tig;
                    float2 cA = *reinterpret_cast<const float2*>(c_s + n0);
                    float2 cB = *reinterpret_cast<const float2*>(c_s + 80 + n0);
                    float ccx = cA.x + cB.x, ccy = cA.y + cB.y;   // = c/2
                    float t0v = tanhap(fmaf(0.5f, acc1[nt][0], ccx));
                    float t1v = tanhap(fmaf(0.5f, acc1[nt][1], ccy));
                    float t2v = tanhap(fmaf(0.5f, acc1[nt][2], ccx));
                    float t3v = tanhap(fmaf(0.5f, acc1[nt][3], ccy));
                    pk_lo[gn] = pack_bf16(t0v, t1v);
                    pk_hi[gn] = pack_bf16(t2v, t3v);
                }
            }

            // ---- layer 2: A = tau (registers), B = W2/2 ----
            float acc2[5][4];
            #pragma unroll
            for (int nt = 0; nt < 5; nt++)
                #pragma unroll
                for (int i = 0; i < 4; i++) acc2[nt][i] = 0.f;

            #pragma unroll
            for (int kc = 0; kc < 5; kc++) {
                const uint32_t off = 32 * kc;
                const uint32_t a0 = pk_lo[2 * kc],     a1 = pk_hi[2 * kc];
                const uint32_t a2 = pk_lo[2 * kc + 1], a3 = pk_hi[2 * kc + 1];
                uint32_t b0, b1r, b2r, b3;
                ldm_x4(b0, b1r, b2r, b3, aC01 + off);
                mma16(acc2[0][0], acc2[0][1], acc2[0][2], acc2[0][3], a0, a1, a2, a3, b0, b1r);
                mma16(acc2[1][0], acc2[1][1], acc2[1][2], acc2[1][3], a0, a1, a2, a3, b2r, b3);
                ldm_x4(b0, b1r, b2r, b3, aC23 + off);
                mma16(acc2[2][0], acc2[2][1], acc2[2][2], acc2[2][3], a0, a1, a2, a3, b0, b1r);
                mma16(acc2[3][0], acc2[3][1], acc2[3][2], acc2[3][3], a0, a1, a2, a3, b2r, b3);
                ldm_x2(b0, b1r, aC4 + off);
                mma16(acc2[4][0], acc2[4][1], acc2[4][2], acc2[4][3], a0, a1, a2, a3, b0, b1r);
            }

            // ---- head: s = Sum q_n (1 + tanh(fma(.5, acc2, r_n))) ----
            float s0 = 0.f, s1 = 0.f;
            #pragma unroll
            for (int nt = 0; nt < 5; nt++) {
                const int n0 = 8 * nt + 2 * tig;
                float2 rr = *reinterpret_cast<const float2*>(b2_s + n0);
                float2 qq = *reinterpret_cast<const float2*>(Wd_s + n0);
                float t00 = tanhap(fmaf(0.5f, acc2[nt][0], rr.x));
                float t01 = tanhap(fmaf(0.5f, acc2[nt][1], rr.y));
                float t10 = tanhap(fmaf(0.5f, acc2[nt][2], rr.x));
                float t11 = tanhap(fmaf(0.5f, acc2[nt][3], rr.y));
                float qc = qq.x + qq.y;
                s0 += qc; s1 += qc;
                s0 = fmaf(qq.x, t00, s0);
                s0 = fmaf(qq.y, t01, s0);
                s1 = fmaf(qq.x, t10, s1);
                s1 = fmaf(qq.y, t11, s1);
            }
            #pragma unroll
            for (int off = 1; off < 4; off <<= 1) {
                s0 += __shfl_xor_sync(0xffffffffu, s0, off);
                s1 += __shfl_xor_sync(0xffffffffu, s1, off);
            }
            if (tig == 0) {
                const int t = t0 + 16 * w + gid;
                sc[t]     = s0;
                sc[t + 8] = s1;
            }
        }

        // ---- stage chunk 1 (rows 128..255, clamped) ----
        if ((ch + 1) < nchunk) {
            __syncthreads();   // B: all K_s reads of this chunk done
            #pragma unroll
            for (int it = 0; it < 8; it++) {
                int r = 128 + srow + 16 * it;
                r = r < T_DIM ? r : T_DIM - 1;
                float4 f = *reinterpret_cast<const float4*>(Kbase + r * H_DIM + scol);
                uint2 u;
                u.x = pack_bf16(f.x, f.y);
                u.y = pack_bf16(f.z, f.w);
                *reinterpret_cast<uint2*>(sdst0 + it * (16 * K_STR)) = u;
            }
        }
    }
    __syncthreads();   // sc[] visible

    // ---- softmax (2 barriers): scale 1/sqrt(64); bd cancels ----
    float v = -INFINITY;
    if (tid < len) v = sc[tid] * 0.125f;
    float mx = v;
    #pragma unroll
    for (int s = 16; s; s >>= 1) mx = fmaxf(mx, __shfl_xor_sync(0xffffffffu, mx, s));
    if (lane == 0) red[w] = mx;
    __syncthreads();
    float M = red[0];
    #pragma unroll
    for (int i = 1; i < 8; i++) M = fmaxf(M, red[i]);

    float e = (tid < len) ? ex2f(1.4426950408889634f * (v - M)) : 0.f;
    if (tid < T_DIM) sc[tid] = e;       // unnormalized
    float s = e;
    #pragma unroll
    for (int o = 16; o; o >>= 1) s += __shfl_xor_sync(0xffffffffu, s, o);
    if (lane == 0) red2[w] = s;
    __syncthreads();                     // sc[] + red2[] visible
    float ssum = red2[0];
    #pragma unroll
    for (int i = 1; i < 8; i++) ssum += red2[i];
    const float inv_sum = 1.f / ssum;

    // ---- out[h] = inv_sum * sum_t e[t]*keys[b,t,h]; float4, 16 t-groups ----
    {
        const int g  = tid >> 4;            // 0..15 t-group
        const int c4 = (tid & 15) << 2;     // h base
        const float* pk = Kbase + g * H_DIM + c4;
        float4 acc = make_float4(0.f, 0.f, 0.f, 0.f);
        for (int t = g; t < len; t += 16) {
            float wt = sc[t];
            float4 k4 = *reinterpret_cast<const float4*>(pk);
            acc.x += wt * k4.x; acc.y += wt * k4.y;
            acc.z += wt * k4.z; acc.w += wt * k4.w;
            pk += 16 * H_DIM;
        }
        *reinterpret_cast<float4*>(obuf + g * 64 + c4) = acc;
        __syncthreads();
        if (tid < H_DIM) {
            float o = 0.f;
            #pragma unroll
            for (int i = 0; i < 16; i++) o += obuf[i * 64 + tid];
            out[b * H_DIM + tid] = inv_sum * o;
        }
    }
}

extern "C" void kernel_launch(void* const* d_in, const int* in_sizes, int n_in,
                              void* d_out, int out_size)
{
    const float* queries = (const float*)d_in[0];
    const float* keys    = (const float*)d_in[1];
    const int*   klen    = (const int*)d_in[2];
    const float* W1      = (const float*)d_in[3];
    const float* b1      = (const float*)d_in[4];
    const float* W2      = (const float*)d_in[5];
    const float* b2      = (const float*)d_in[6];
    const float* Wd      = (const float*)d_in[7];
    // d_in[8] = bd : uniform shift, cancels in softmax
    float* out = (float*)d_out;

    const int B = in_sizes[2];  // keys_length count
    const size_t smem = SMEM_FLOATS * sizeof(float);
    cudaFuncSetAttribute(seqatt_kernel,
                         cudaFuncAttributeMaxDynamicSharedMemorySize, (int)smem);
    seqatt_kernel<<<B, 256, smem>>>(queries, keys, klen, W1, b1, W2, b2, Wd, out);
}

// round 17
// speedup vs baseline: 1.0496x; 1.0496x over previous
#include <cuda_runtime.h>
#include <cuda_bf16.h>
#include <math.h>
#include <stdint.h>

// SequenceAttLayer: B=4096, T=200, H=64; MLP 256->80->40->1, masked softmax, att@keys.
// Algebra: x=[q,k,q-k,q*k];  x.W1 = k.(W1b-W1c + diag(q).W1d) + [q.(W1a+W1c)+b1]
// Round 17: whole-K residency. All <=208 K rows staged once (merged into phase-0
// barrier); warps then stream their m-tiles {w, w+8} with NO block barriers in the
// compute section (cross-tile ILP). Fused layers as in round 14 (H1 in registers).

#define T_DIM 200
#define H_DIM 64
#define D1 80
#define D2 40

#define K_STR   72
#define WT_STR  72
#define W2T_STR 88

// shared layout (float offsets; bf16 regions are 2x elements)
#define OFF_KS    0        // 208*72 bf16 = 7488 f
#define OFF_WT    7488     // 80*72 bf16 = 2880 f
#define OFF_W2T   10368    // 40*88 bf16 = 1760 f
#define OFF_C     12128    // 160 (two halves)
#define OFF_B2    12288    // 40
#define OFF_WD    12328    // 40
#define OFF_Q     12368    // 64
#define OFF_SC    12432    // 208
#define OFF_RED   12640    // 8
#define OFF_RED2  12648    // 8
#define OFF_OBUF  12656    // 16*64 = 1024
#define SMEM_FLOATS 13680  // 54720 B -> 4 CTAs/SM (218.9 KB)

typedef __nv_bfloat16 bf16;

__device__ __forceinline__ uint32_t cvsm(const void* p) {
    return (uint32_t)__cvta_generic_to_shared(p);
}
__device__ __forceinline__ void ldm_x4(uint32_t& r0, uint32_t& r1,
                                       uint32_t& r2, uint32_t& r3, uint32_t a) {
    asm volatile("ldmatrix.sync.aligned.m8n8.x4.shared.b16 {%0,%1,%2,%3}, [%4];"
                 : "=r"(r0), "=r"(r1), "=r"(r2), "=r"(r3) : "r"(a));
}
__device__ __forceinline__ void ldm_x2(uint32_t& r0, uint32_t& r1, uint32_t a) {
    asm volatile("ldmatrix.sync.aligned.m8n8.x2.shared.b16 {%0,%1}, [%2];"
                 : "=r"(r0), "=r"(r1) : "r"(a));
}
__device__ __forceinline__ void mma16(float& d0, float& d1, float& d2, float& d3,
                                      uint32_t a0, uint32_t a1, uint32_t a2, uint32_t a3,
                                      uint32_t b0, uint32_t b1) {
    asm("mma.sync.aligned.m16n8k16.row.col.f32.bf16.bf16.f32 "
        "{%0,%1,%2,%3}, {%4,%5,%6,%7}, {%8,%9}, {%0,%1,%2,%3};"
        : "+f"(d0), "+f"(d1), "+f"(d2), "+f"(d3)
        : "r"(a0), "r"(a1), "r"(a2), "r"(a3), "r"(b0), "r"(b1));
}
__device__ __forceinline__ uint32_t pack_bf16(float lo, float hi) {
    uint32_t r;
    asm("cvt.rn.bf16x2.f32 %0, %1, %2;" : "=r"(r) : "f"(hi), "f"(lo));
    return r;
}
__device__ __forceinline__ float ex2f(float x) {
    float r;
    asm("ex2.approx.f32 %0, %1;" : "=f"(r) : "f"(x));
    return r;
}
__device__ __forceinline__ float sigf(float z) {
    float e = ex2f(-1.4426950408889634f * z);
    float r;
    asm("rcp.approx.f32 %0, %1;" : "=f"(r) : "f"(1.f + e));
    return r;
}

__global__ __launch_bounds__(256, 4)
void seqatt_kernel(const float* __restrict__ queries,
                   const float* __restrict__ keys,
                   const int* __restrict__ keys_length,
                   const float* __restrict__ W1,
                   const float* __restrict__ b1,
                   const float* __restrict__ W2,
                   const float* __restrict__ b2,
                   const float* __restrict__ Wd,
                   float* __restrict__ out)
{
    extern __shared__ float sm[];
    bf16* K_s   = reinterpret_cast<bf16*>(sm + OFF_KS);
    bf16* W_t   = reinterpret_cast<bf16*>(sm + OFF_WT);
    bf16* W2_t  = reinterpret_cast<bf16*>(sm + OFF_W2T);
    float* c_s  = sm + OFF_C;
    float* b2_s = sm + OFF_B2;
    float* Wd_s = sm + OFF_WD;
    float* q_s  = sm + OFF_Q;
    float* sc   = sm + OFF_SC;
    float* red  = sm + OFF_RED;
    float* red2 = sm + OFF_RED2;
    float* obuf = sm + OFF_OBUF;

    const int b   = blockIdx.x;
    const int tid = threadIdx.x;
    // keys_length is int32 on device (JAX x64-disabled downcasts int64->int32).
    int len = keys_length[b];
    len = len < 1 ? 1 : (len > T_DIM ? T_DIM : len);
    const int rows_needed = (len + 15) & ~15;   // <= 208

    const float* Kbase = keys + (size_t)b * T_DIM * H_DIM;

    // ---- phase 0a: q, b2/Wd, W2_t, and ALL K rows (one pass) ----
    if (tid < H_DIM) q_s[tid] = queries[b * H_DIM + tid];
    if (tid < D2) { b2_s[tid] = b2[tid]; Wd_s[tid] = Wd[tid]; }
    for (int i = tid; i < D1 * (D2 / 2); i += 256) {     // W2_t[n][j] = W2[j][n]
        int j = i / (D2 / 2), n2 = i - (i / (D2 / 2)) * (D2 / 2);
        float2 v = *reinterpret_cast<const float2*>(W2 + j * D2 + 2 * n2);
        W2_t[(2 * n2)     * W2T_STR + j] = __float2bfloat16(v.x);
        W2_t[(2 * n2 + 1) * W2T_STR + j] = __float2bfloat16(v.y);
    }
    {
        const int srow = tid >> 4;              // 0..15
        const int scol = (tid & 15) << 2;
        bf16* sdst0 = K_s + srow * K_STR + scol;
        for (int it = 0; srow + 16 * it < rows_needed; it++) {
            int r = srow + 16 * it;
            int rg = r < T_DIM ? r : T_DIM - 1;  // clamp (masked rows only)
            float4 f = *reinterpret_cast<const float4*>(Kbase + rg * H_DIM + scol);
            uint2 u;
            u.x = pack_bf16(f.x, f.y);
            u.y = pack_bf16(f.z, f.w);
            *reinterpret_cast<uint2*>(sdst0 + it * (16 * K_STR)) = u;
        }
    }
    __syncthreads();   // q_s ready for W_t/c build

    // ---- phase 0b: W_t (bf16) and c halves (fp32) ----
    for (int i = tid; i < H_DIM * (D1 / 2); i += 256) {  // W_t[j][h]
        int h = i / (D1 / 2), j2 = i - (i / (D1 / 2)) * (D1 / 2);
        float2 wb = *reinterpret_cast<const float2*>(W1 + (64  + h) * D1 + 2 * j2);
        float2 wc = *reinterpret_cast<const float2*>(W1 + (128 + h) * D1 + 2 * j2);
        float2 wd = *reinterpret_cast<const float2*>(W1 + (192 + h) * D1 + 2 * j2);
        float qh = q_s[h];
        W_t[(2 * j2)     * WT_STR + h] = __float2bfloat16(wb.x - wc.x + qh * wd.x);
        W_t[(2 * j2 + 1) * WT_STR + h] = __float2bfloat16(wb.y - wc.y + qh * wd.y);
    }
    if (tid < 160) {   // c halves, summed in the layer-1 epilogue
        int seg = (tid >= 80) ? 1 : 0;
        int j = tid - 80 * seg;
        float acc = seg ? 0.f : b1[j];
        const float* p1 = W1 + (32 * seg) * D1 + j;
        const float* p2 = W1 + (128 + 32 * seg) * D1 + j;
        const float* qq = q_s + 32 * seg;
        #pragma unroll 8
        for (int h = 0; h < 32; h++)
            acc += qq[h] * (p1[h * D1] + p2[h * D1]);
        c_s[seg * 80 + j] = acc;
    }
    __syncthreads();   // everything resident: K_s, W_t, W2_t, c, scalars

    const int w    = tid >> 5;
    const int lane = tid & 31;
    const int gid  = lane >> 2;
    const int tig  = lane & 3;

    const int r8  = lane & 7;
    const int mi  = lane >> 3;
    const int mi2 = mi & 1;

    // base fragment addresses (tile 0); per-tile add 16 rows
    const uint32_t aA_base = cvsm(K_s) + 2 * ((r8 + ((mi & 1) << 3)) * K_STR + ((mi >> 1) << 3));
    const uint32_t TILE_BYTES = 2 * (16 * K_STR);
    const uint32_t aB01 = cvsm(W_t) + 2 * ((8 * (mi >> 1) + r8) * WT_STR + ((mi & 1) << 3));
    const uint32_t aB23 = aB01 + 2 * (16 * WT_STR);
    const uint32_t aB4  = cvsm(W_t) + 2 * ((8 * 4 + r8) * WT_STR + (mi2 << 3));
    const uint32_t NBH  = 2 * (40 * WT_STR);   // bytes per n-half (5 tiles)
    const uint32_t aC01 = cvsm(W2_t) + 2 * ((8 * (mi >> 1) + r8) * W2T_STR + ((mi & 1) << 3));
    const uint32_t aC23 = aC01 + 2 * (16 * W2T_STR);
    const uint32_t aC4  = cvsm(W2_t) + 2 * ((8 * 4 + r8) * W2T_STR + (mi2 << 3));

    // ---- compute: warp processes m-tiles w and w+8, no block barriers ----
    const int ntiles = rows_needed >> 4;        // ceil(len/16) <= 13
    #pragma unroll
    for (int pass = 0; pass < 2; pass++) {
        const int tw = w + 8 * pass;
        if (tw >= ntiles) continue;
        const uint32_t aA = aA_base + (uint32_t)tw * TILE_BYTES;

        // ---- layer 1: two n-half passes; sig packed into layer-2 A-frags ----
        uint32_t pk_lo[10], pk_hi[10];
        #pragma unroll
        for (int nh = 0; nh < 2; nh++) {
            float acc1[5][4];
            #pragma unroll
            for (int nt = 0; nt < 5; nt++)
                #pragma unroll
                for (int i = 0; i < 4; i++) acc1[nt][i] = 0.f;

            const uint32_t bb0 = aB01 + nh * NBH;
            const uint32_t bb2 = aB23 + nh * NBH;
            const uint32_t bb4 = aB4  + nh * NBH;
            #pragma unroll
            for (int ks = 0; ks < 4; ks++) {
                const uint32_t off = 32 * ks;
                uint32_t a0, a1, a2, a3;
                ldm_x4(a0, a1, a2, a3, aA + off);
                uint32_t b0, b1r, b2r, b3;
                ldm_x4(b0, b1r, b2r, b3, bb0 + off);
                mma16(acc1[0][0], acc1[0][1], acc1[0][2], acc1[0][3], a0, a1, a2, a3, b0, b1r);
                mma16(acc1[1][0], acc1[1][1], acc1[1][2], acc1[1][3], a0, a1, a2, a3, b2r, b3);
                ldm_x4(b0, b1r, b2r, b3, bb2 + off);
                mma16(acc1[2][0], acc1[2][1], acc1[2][2], acc1[2][3], a0, a1, a2, a3, b0, b1r);
                mma16(acc1[3][0], acc1[3][1], acc1[3][2], acc1[3][3], a0, a1, a2, a3, b2r, b3);
                ldm_x2(b0, b1r, bb4 + off);
                mma16(acc1[4][0], acc1[4][1], acc1[4][2], acc1[4][3], a0, a1, a2, a3, b0, b1r);
            }
            #pragma unroll
            for (int nt = 0; nt < 5; nt++) {
                const int gn = 5 * nh + nt;
                const int n0 = 8 * gn + 2 * tig;
                float2 cA = *reinterpret_cast<const float2*>(c_s + n0);
                float2 cB = *reinterpret_cast<const float2*>(c_s + 80 + n0);
                float ccx = cA.x + cB.x, ccy = cA.y + cB.y;
                pk_lo[gn] = pack_bf16(sigf(acc1[nt][0] + ccx), sigf(acc1[nt][1] + ccy));
                pk_hi[gn] = pack_bf16(sigf(acc1[nt][2] + ccx), sigf(acc1[nt][3] + ccy));
            }
        }

        // ---- layer 2: A-fragments already in registers ----
        float acc2[5][4];
        #pragma unroll
        for (int nt = 0; nt < 5; nt++)
            #pragma unroll
            for (int i = 0; i < 4; i++) acc2[nt][i] = 0.f;

        #pragma unroll
        for (int kc = 0; kc < 5; kc++) {
            const uint32_t off = 32 * kc;
            const uint32_t a0 = pk_lo[2 * kc],     a1 = pk_hi[2 * kc];
            const uint32_t a2 = pk_lo[2 * kc + 1], a3 = pk_hi[2 * kc + 1];
            uint32_t b0, b1r, b2r, b3;
            ldm_x4(b0, b1r, b2r, b3, aC01 + off);
            mma16(acc2[0][0], acc2[0][1], acc2[0][2], acc2[0][3], a0, a1, a2, a3, b0, b1r);
            mma16(acc2[1][0], acc2[1][1], acc2[1][2], acc2[1][3], a0, a1, a2, a3, b2r, b3);
            ldm_x4(b0, b1r, b2r, b3, aC23 + off);
            mma16(acc2[2][0], acc2[2][1], acc2[2][2], acc2[2][3], a0, a1, a2, a3, b0, b1r);
            mma16(acc2[3][0], acc2[3][1], acc2[3][2], acc2[3][3], a0, a1, a2, a3, b2r, b3);
            ldm_x2(b0, b1r, aC4 + off);
            mma16(acc2[4][0], acc2[4][1], acc2[4][2], acc2[4][3], a0, a1, a2, a3, b0, b1r);
        }

        // ---- head: scores complete within the warp ----
        float s0 = 0.f, s1 = 0.f;
        #pragma unroll
        for (int nt = 0; nt < 5; nt++) {
            const int n0 = 8 * nt + 2 * tig;
            float2 bb = *reinterpret_cast<const float2*>(b2_s + n0);
            float2 wd = *reinterpret_cast<const float2*>(Wd_s + n0);
            s0 += sigf(acc2[nt][0] + bb.x) * wd.x + sigf(acc2[nt][1] + bb.y) * wd.y;
            s1 += sigf(acc2[nt][2] + bb.x) * wd.x + sigf(acc2[nt][3] + bb.y) * wd.y;
        }
        #pragma unroll
        for (int off = 1; off < 4; off <<= 1) {
            s0 += __shfl_xor_sync(0xffffffffu, s0, off);
            s1 += __shfl_xor_sync(0xffffffffu, s1, off);
        }
        if (tig == 0) {
            const int t = 16 * tw + gid;
            sc[t]     = s0;
            sc[t + 8] = s1;
        }
    }
    __syncthreads();   // sc[] visible

    // ---- softmax (2 barriers): scale 1/sqrt(64); bd cancels ----
    float v = -INFINITY;
    if (tid < len) v = sc[tid] * 0.125f;
    float mx = v;
    #pragma unroll
    for (int s = 16; s; s >>= 1) mx = fmaxf(mx, __shfl_xor_sync(0xffffffffu, mx, s));
    if (lane == 0) red[w] = mx;
    __syncthreads();
    float M = red[0];
    #pragma unroll
    for (int i = 1; i < 8; i++) M = fmaxf(M, red[i]);

    float e = (tid < len) ? ex2f(1.4426950408889634f * (v - M)) : 0.f;
    if (tid < T_DIM) sc[tid] = e;       // unnormalized
    float s = e;
    #pragma unroll
    for (int o = 16; o; o >>= 1) s += __shfl_xor_sync(0xffffffffu, s, o);
    if (lane == 0) red2[w] = s;
    __syncthreads();                     // sc[] + red2[] visible
    float ssum = red2[0];
    #pragma unroll
    for (int i = 1; i < 8; i++) ssum += red2[i];
    const float inv_sum = 1.f / ssum;

    // ---- out[h] = inv_sum * sum_t e[t]*keys[b,t,h]; float4, 16 t-groups ----
    {
        const int g  = tid >> 4;            // 0..15 t-group
        const int c4 = (tid & 15) << 2;     // h base
        const float* pk = Kbase + g * H_DIM + c4;
        float4 acc = make_float4(0.f, 0.f, 0.f, 0.f);
        for (int t = g; t < len; t += 16) {
            float wt = sc[t];
            float4 k4 = *reinterpret_cast<const float4*>(pk);
            acc.x += wt * k4.x; acc.y += wt * k4.y;
            acc.z += wt * k4.z; acc.w += wt * k4.w;
            pk += 16 * H_DIM;
        }
        *reinterpret_cast<float4*>(obuf + g * 64 + c4) = acc;
        __syncthreads();
        if (tid < H_DIM) {
            float o = 0.f;
            #pragma unroll
            for (int i = 0; i < 16; i++) o += obuf[i * 64 + tid];
            out[b * H_DIM + tid] = inv_sum * o;
        }
    }
}

extern "C" void kernel_launch(void* const* d_in, const int* in_sizes, int n_in,
                              void* d_out, int out_size)
{
    const float* queries = (const float*)d_in[0];
    const float* keys    = (const float*)d_in[1];
    const int*   klen    = (const int*)d_in[2];
    const float* W1      = (const float*)d_in[3];
    const float* b1      = (const float*)d_in[4];
    const float* W2      = (const float*)d_in[5];
    const float* b2      = (const float*)d_in[6];
    const float* Wd      = (const float*)d_in[7];
    // d_in[8] = bd : uniform shift, cancels in softmax
    float* out = (float*)d_out;

    const int B = in_sizes[2];  // keys_length count
    const size_t smem = SMEM_FLOATS * sizeof(float);
    cudaFuncSetAttribute(seqatt_kernel,
                         cudaFuncAttributeMaxDynamicSharedMemorySize, (int)smem);
    seqatt_kernel<<<B, 256, smem>>>(queries, keys, klen, W1, b1, W2, b2, Wd, out);
}